// round 1
// baseline (speedup 1.0000x reference)
#include <cuda_runtime.h>
#include <cstdint>

#define S_TOK   8192
#define DMODEL  2048
#define DFF     8192
#define NEXP    8
#define TOPK    2
#define CAP     2560   // ceil(1.25 * 8192*2 / 8)

// ---------------- scratch (static device globals; no runtime alloc) ----------------
__device__ float g_H[(size_t)NEXP * CAP * DFF];        // relu(x@w1) per expert slot
__device__ float g_Eout[(size_t)NEXP * CAP * DMODEL];  // expert output per slot
__device__ int   g_disp_tok[NEXP * CAP];               // token index gathered into each slot
__device__ int   g_slot[S_TOK * TOPK];                 // e*CAP+pos, or -1 if dropped
__device__ float g_wt[S_TOK * TOPK];                   // gate weight (0 if dropped)
__device__ int   g_topk_idx[S_TOK * TOPK];
__device__ float g_topk_gate[S_TOK * TOPK];

// ---------------- 1) gating: logits -> softmax -> top-2 (one warp per token) -------
__global__ void gate_kernel(const float* __restrict__ x, const float* __restrict__ Wg) {
    int gw   = (blockIdx.x * blockDim.x + threadIdx.x) >> 5;
    int lane = threadIdx.x & 31;
    if (gw >= S_TOK) return;
    const float* xr = x + (size_t)gw * DMODEL;

    float acc[NEXP];
#pragma unroll
    for (int e = 0; e < NEXP; e++) acc[e] = 0.f;

    for (int d = lane; d < DMODEL; d += 32) {
        float xv = xr[d];
        const float* wrow = Wg + (size_t)d * NEXP;
#pragma unroll
        for (int e = 0; e < NEXP; e++) acc[e] = fmaf(xv, wrow[e], acc[e]);
    }
#pragma unroll
    for (int off = 16; off; off >>= 1) {
#pragma unroll
        for (int e = 0; e < NEXP; e++)
            acc[e] += __shfl_xor_sync(0xffffffffu, acc[e], off);
    }
    if (lane == 0) {
        float mx = acc[0];
#pragma unroll
        for (int e = 1; e < NEXP; e++) mx = fmaxf(mx, acc[e]);
        float p[NEXP], den = 0.f;
#pragma unroll
        for (int e = 0; e < NEXP; e++) { p[e] = expf(acc[e] - mx); den += p[e]; }
        float inv = 1.0f / den;

        // top-1 (strict > keeps lowest index on ties, matching lax.top_k)
        int i0 = 0; float v0 = p[0];
#pragma unroll
        for (int e = 1; e < NEXP; e++) if (p[e] > v0) { v0 = p[e]; i0 = e; }
        // top-2
        int i1 = (i0 == 0) ? 1 : 0; float v1 = p[i1];
#pragma unroll
        for (int e = 0; e < NEXP; e++)
            if (e != i0 && p[e] > v1) { v1 = p[e]; i1 = e; }

        g_topk_idx[gw * 2 + 0]  = i0;
        g_topk_idx[gw * 2 + 1]  = i1;
        g_topk_gate[gw * 2 + 0] = v0 * inv;
        g_topk_gate[gw * 2 + 1] = v1 * inv;
    }
}

// ---------------- 2) routing: ordered per-expert cumsum + capacity ------------------
// Single block, 512 threads, 32 assignments each. Exactly reproduces the
// reference's flat-order (token-major) position-within-expert-queue semantics.
__global__ void route_kernel() {
    __shared__ int counts[512][NEXP];
    const int t = threadIdx.x;

    // init dispatch slots to token 0 (sentinel % S == 0 in the reference;
    // empty-slot FFN results are never read by combine)
    for (int i = t; i < NEXP * CAP; i += 512) g_disp_tok[i] = 0;

    int base = t * 32;
    int cnt[NEXP];
#pragma unroll
    for (int e = 0; e < NEXP; e++) cnt[e] = 0;
    int eidx[32];
#pragma unroll
    for (int i = 0; i < 32; i++) {
        eidx[i] = g_topk_idx[base + i];
        cnt[eidx[i]]++;
    }
#pragma unroll
    for (int e = 0; e < NEXP; e++) counts[t][e] = cnt[e];
    __syncthreads();

    // exclusive scan across threads, one expert per thread (serial, tiny)
    if (t < NEXP) {
        int run = 0;
        for (int i = 0; i < 512; i++) {
            int v = counts[i][t];
            counts[i][t] = run;
            run += v;
        }
    }
    __syncthreads();

    int run[NEXP];
#pragma unroll
    for (int e = 0; e < NEXP; e++) run[e] = counts[t][e];
#pragma unroll
    for (int i = 0; i < 32; i++) {
        int idx = base + i;
        int e   = eidx[i];
        int pos = run[e]++;
        if (pos < CAP) {
            int s = idx >> 1;             // flat i = s*K + j
            g_disp_tok[e * CAP + pos] = s;
            g_slot[idx] = e * CAP + pos;
            g_wt[idx]   = g_topk_gate[idx];
        } else {
            g_slot[idx] = -1;
            g_wt[idx]   = 0.f;
        }
    }
}

// ---------------- 3) GEMM1: H[e,c,:] = relu(x[tok(e,c),:] @ w1[e]) ------------------
// 128x128x16 tile, 256 threads, 8x8 register blocking, fused gather on A rows.
__global__ __launch_bounds__(256, 2)
void gemm1_kernel(const float* __restrict__ x, const float* __restrict__ w1) {
    const int e  = blockIdx.z;
    const int m0 = blockIdx.y * 128;
    const int n0 = blockIdx.x * 128;

    __shared__ float As[16][128];
    __shared__ float Bs[16][128];

    const int tid = threadIdx.x;
    const int tx = tid & 15, ty = tid >> 4;

    const int ar = tid >> 2;          // 0..63
    const int ak = (tid & 3) << 2;    // 0,4,8,12
    const int tok0 = g_disp_tok[e * CAP + m0 + ar];
    const int tok1 = g_disp_tok[e * CAP + m0 + ar + 64];
    const float* arow0 = x + (size_t)tok0 * DMODEL;
    const float* arow1 = x + (size_t)tok1 * DMODEL;

    const int br = tid >> 5;          // 0..7
    const int bn = (tid & 31) << 2;   // 0..124
    const float* Bbase = w1 + (size_t)e * DMODEL * DFF + n0;

    float acc[8][8];
#pragma unroll
    for (int i = 0; i < 8; i++)
#pragma unroll
        for (int j = 0; j < 8; j++) acc[i][j] = 0.f;

    for (int k0 = 0; k0 < DMODEL; k0 += 16) {
        float4 a0 = *(const float4*)(arow0 + k0 + ak);
        float4 a1 = *(const float4*)(arow1 + k0 + ak);
        As[ak + 0][ar] = a0.x; As[ak + 1][ar] = a0.y;
        As[ak + 2][ar] = a0.z; As[ak + 3][ar] = a0.w;
        As[ak + 0][ar + 64] = a1.x; As[ak + 1][ar + 64] = a1.y;
        As[ak + 2][ar + 64] = a1.z; As[ak + 3][ar + 64] = a1.w;

        float4 b0 = *(const float4*)(Bbase + (size_t)(k0 + br) * DFF + bn);
        float4 b1 = *(const float4*)(Bbase + (size_t)(k0 + br + 8) * DFF + bn);
        *(float4*)&Bs[br][bn]     = b0;
        *(float4*)&Bs[br + 8][bn] = b1;
        __syncthreads();

#pragma unroll
        for (int kk = 0; kk < 16; kk++) {
            float ra[8], rb[8];
#pragma unroll
            for (int i = 0; i < 8; i++) ra[i] = As[kk][ty * 8 + i];
#pragma unroll
            for (int j = 0; j < 8; j++) rb[j] = Bs[kk][tx * 8 + j];
#pragma unroll
            for (int i = 0; i < 8; i++)
#pragma unroll
                for (int j = 0; j < 8; j++)
                    acc[i][j] = fmaf(ra[i], rb[j], acc[i][j]);
        }
        __syncthreads();
    }

    float* Hout = g_H + ((size_t)e * CAP + m0) * DFF + n0;
#pragma unroll
    for (int i = 0; i < 8; i++) {
        float* row = Hout + (size_t)(ty * 8 + i) * DFF + tx * 8;
#pragma unroll
        for (int j = 0; j < 8; j += 4) {
            float4 v;
            v.x = fmaxf(acc[i][j + 0], 0.f);
            v.y = fmaxf(acc[i][j + 1], 0.f);
            v.z = fmaxf(acc[i][j + 2], 0.f);
            v.w = fmaxf(acc[i][j + 3], 0.f);
            *(float4*)(row + j) = v;
        }
    }
}

// ---------------- 4) GEMM2: Eout[e,c,:] = H[e,c,:] @ w2[e] --------------------------
__global__ __launch_bounds__(256, 2)
void gemm2_kernel(const float* __restrict__ w2) {
    const int e  = blockIdx.z;
    const int m0 = blockIdx.y * 128;
    const int n0 = blockIdx.x * 128;

    __shared__ float As[16][128];
    __shared__ float Bs[16][128];

    const int tid = threadIdx.x;
    const int tx = tid & 15, ty = tid >> 4;

    const int ar = tid >> 2;
    const int ak = (tid & 3) << 2;
    const float* arow0 = g_H + ((size_t)e * CAP + m0 + ar) * DFF;
    const float* arow1 = g_H + ((size_t)e * CAP + m0 + ar + 64) * DFF;

    const int br = tid >> 5;
    const int bn = (tid & 31) << 2;
    const float* Bbase = w2 + (size_t)e * DFF * DMODEL + n0;

    float acc[8][8];
#pragma unroll
    for (int i = 0; i < 8; i++)
#pragma unroll
        for (int j = 0; j < 8; j++) acc[i][j] = 0.f;

    for (int k0 = 0; k0 < DFF; k0 += 16) {
        float4 a0 = *(const float4*)(arow0 + k0 + ak);
        float4 a1 = *(const float4*)(arow1 + k0 + ak);
        As[ak + 0][ar] = a0.x; As[ak + 1][ar] = a0.y;
        As[ak + 2][ar] = a0.z; As[ak + 3][ar] = a0.w;
        As[ak + 0][ar + 64] = a1.x; As[ak + 1][ar + 64] = a1.y;
        As[ak + 2][ar + 64] = a1.z; As[ak + 3][ar + 64] = a1.w;

        float4 b0 = *(const float4*)(Bbase + (size_t)(k0 + br) * DMODEL + bn);
        float4 b1 = *(const float4*)(Bbase + (size_t)(k0 + br + 8) * DMODEL + bn);
        *(float4*)&Bs[br][bn]     = b0;
        *(float4*)&Bs[br + 8][bn] = b1;
        __syncthreads();

#pragma unroll
        for (int kk = 0; kk < 16; kk++) {
            float ra[8], rb[8];
#pragma unroll
            for (int i = 0; i < 8; i++) ra[i] = As[kk][ty * 8 + i];
#pragma unroll
            for (int j = 0; j < 8; j++) rb[j] = Bs[kk][tx * 8 + j];
#pragma unroll
            for (int i = 0; i < 8; i++)
#pragma unroll
                for (int j = 0; j < 8; j++)
                    acc[i][j] = fmaf(ra[i], rb[j], acc[i][j]);
        }
        __syncthreads();
    }

    float* Co = g_Eout + ((size_t)e * CAP + m0) * DMODEL + n0;
#pragma unroll
    for (int i = 0; i < 8; i++) {
        float* row = Co + (size_t)(ty * 8 + i) * DMODEL + tx * 8;
#pragma unroll
        for (int j = 0; j < 8; j += 4) {
            float4 v;
            v.x = acc[i][j + 0]; v.y = acc[i][j + 1];
            v.z = acc[i][j + 2]; v.w = acc[i][j + 3];
            *(float4*)(row + j) = v;
        }
    }
}

// ---------------- 5) combine: out[s,:] = sum_j w_j * Eout[slot_j,:] -----------------
__global__ void combine_kernel(float* __restrict__ out) {
    const int s = blockIdx.x;
    const int sl0 = g_slot[s * 2 + 0];
    const int sl1 = g_slot[s * 2 + 1];
    const float w0 = g_wt[s * 2 + 0];
    const float w1 = g_wt[s * 2 + 1];

    const float4* e0 = (sl0 >= 0) ? (const float4*)(g_Eout + (size_t)sl0 * DMODEL) : nullptr;
    const float4* e1 = (sl1 >= 0) ? (const float4*)(g_Eout + (size_t)sl1 * DMODEL) : nullptr;
    float4* dst = (float4*)(out + (size_t)s * DMODEL);

    for (int m = threadIdx.x; m < DMODEL / 4; m += blockDim.x) {
        float4 r = make_float4(0.f, 0.f, 0.f, 0.f);
        if (e0) {
            float4 v = e0[m];
            r.x = fmaf(w0, v.x, r.x); r.y = fmaf(w0, v.y, r.y);
            r.z = fmaf(w0, v.z, r.z); r.w = fmaf(w0, v.w, r.w);
        }
        if (e1) {
            float4 v = e1[m];
            r.x = fmaf(w1, v.x, r.x); r.y = fmaf(w1, v.y, r.y);
            r.z = fmaf(w1, v.z, r.z); r.w = fmaf(w1, v.w, r.w);
        }
        dst[m] = r;
    }
}

// ---------------- launch -----------------------------------------------------------
extern "C" void kernel_launch(void* const* d_in, const int* in_sizes, int n_in,
                              void* d_out, int out_size) {
    const float* x  = (const float*)d_in[0];
    const float* Wg = (const float*)d_in[1];
    const float* w1 = (const float*)d_in[2];
    const float* w2 = (const float*)d_in[3];
    float* out = (float*)d_out;

    gate_kernel<<<(S_TOK * 32 + 255) / 256, 256>>>(x, Wg);
    route_kernel<<<1, 512>>>();

    dim3 g1(DFF / 128, CAP / 128, NEXP);     // (64, 20, 8)
    gemm1_kernel<<<g1, 256>>>(x, w1);

    dim3 g2(DMODEL / 128, CAP / 128, NEXP);  // (16, 20, 8)
    gemm2_kernel<<<g2, 256>>>(w2);

    combine_kernel<<<S_TOK, 128>>>(out);
}

// round 2
// speedup vs baseline: 3.2821x; 3.2821x over previous
#include <cuda_runtime.h>
#include <cstdint>

#define S_TOK   8192
#define DMODEL  2048
#define DFF     8192
#define NEXP    8
#define CAP     2560   // ceil(1.25 * 8192*2 / 8)

// ---------------- scratch (static device globals; no runtime alloc) ----------------
__device__ float g_H[(size_t)NEXP * CAP * DFF];        // relu(x@w1) per expert slot
__device__ float g_Eout[(size_t)NEXP * CAP * DMODEL];  // expert output per slot
__device__ int   g_disp_tok[NEXP * CAP];               // token index gathered into each slot
__device__ int   g_slot[S_TOK * 2];                    // e*CAP+pos, or -1 if dropped
__device__ float g_wt[S_TOK * 2];                      // gate weight (0 if dropped)
__device__ int   g_topk_idx[S_TOK * 2];
__device__ float g_topk_gate[S_TOK * 2];

// ---------------- PTX helpers -------------------------------------------------------
__device__ __forceinline__ void cp_async16(uint32_t smem, const void* gmem) {
    asm volatile("cp.async.cg.shared.global [%0], [%1], 16;\n" :: "r"(smem), "l"(gmem));
}
__device__ __forceinline__ void cp_commit() {
    asm volatile("cp.async.commit_group;\n" ::);
}
template <int N>
__device__ __forceinline__ void cp_wait() {
    asm volatile("cp.async.wait_group %0;\n" :: "n"(N));
}
__device__ __forceinline__ uint32_t f2tf(float f) {
    uint32_t r;
    asm("cvt.rna.tf32.f32 %0, %1;\n" : "=r"(r) : "f"(f));
    return r;
}
__device__ __forceinline__ void mma_tf32(float d[4], const uint32_t a[4], const uint32_t b[2]) {
    asm volatile(
        "mma.sync.aligned.m16n8k8.row.col.f32.tf32.tf32.f32 "
        "{%0,%1,%2,%3}, {%4,%5,%6,%7}, {%8,%9}, {%0,%1,%2,%3};\n"
        : "+f"(d[0]), "+f"(d[1]), "+f"(d[2]), "+f"(d[3])
        : "r"(a[0]), "r"(a[1]), "r"(a[2]), "r"(a[3]), "r"(b[0]), "r"(b[1]));
}

// ---------------- 1) gating: logits -> softmax -> top-2 (one warp per token) -------
__global__ void gate_kernel(const float* __restrict__ x, const float* __restrict__ Wg) {
    int gw   = (blockIdx.x * blockDim.x + threadIdx.x) >> 5;
    int lane = threadIdx.x & 31;
    if (gw >= S_TOK) return;
    const float* xr = x + (size_t)gw * DMODEL;

    float acc[NEXP];
#pragma unroll
    for (int e = 0; e < NEXP; e++) acc[e] = 0.f;

    for (int d = lane; d < DMODEL; d += 32) {
        float xv = xr[d];
        const float* wrow = Wg + (size_t)d * NEXP;
#pragma unroll
        for (int e = 0; e < NEXP; e++) acc[e] = fmaf(xv, wrow[e], acc[e]);
    }
#pragma unroll
    for (int off = 16; off; off >>= 1) {
#pragma unroll
        for (int e = 0; e < NEXP; e++)
            acc[e] += __shfl_xor_sync(0xffffffffu, acc[e], off);
    }
    if (lane == 0) {
        float mx = acc[0];
#pragma unroll
        for (int e = 1; e < NEXP; e++) mx = fmaxf(mx, acc[e]);
        float p[NEXP], den = 0.f;
#pragma unroll
        for (int e = 0; e < NEXP; e++) { p[e] = expf(acc[e] - mx); den += p[e]; }
        float inv = 1.0f / den;

        int i0 = 0; float v0 = p[0];
#pragma unroll
        for (int e = 1; e < NEXP; e++) if (p[e] > v0) { v0 = p[e]; i0 = e; }
        int i1 = (i0 == 0) ? 1 : 0; float v1 = p[i1];
#pragma unroll
        for (int e = 0; e < NEXP; e++)
            if (e != i0 && p[e] > v1) { v1 = p[e]; i1 = e; }

        g_topk_idx[gw * 2 + 0]  = i0;
        g_topk_idx[gw * 2 + 1]  = i1;
        g_topk_gate[gw * 2 + 0] = v0 * inv;
        g_topk_gate[gw * 2 + 1] = v1 * inv;
    }
}

// ---------------- 2) routing: ordered per-expert cumsum + capacity ------------------
__global__ void route_kernel() {
    __shared__ int counts[512][NEXP];
    const int t = threadIdx.x;

    for (int i = t; i < NEXP * CAP; i += 512) g_disp_tok[i] = 0;

    int base = t * 32;
    int cnt[NEXP];
#pragma unroll
    for (int e = 0; e < NEXP; e++) cnt[e] = 0;
    int eidx[32];
#pragma unroll
    for (int i = 0; i < 32; i++) {
        eidx[i] = g_topk_idx[base + i];
        cnt[eidx[i]]++;
    }
#pragma unroll
    for (int e = 0; e < NEXP; e++) counts[t][e] = cnt[e];
    __syncthreads();

    if (t < NEXP) {
        int run = 0;
        for (int i = 0; i < 512; i++) {
            int v = counts[i][t];
            counts[i][t] = run;
            run += v;
        }
    }
    __syncthreads();

    int run[NEXP];
#pragma unroll
    for (int e = 0; e < NEXP; e++) run[e] = counts[t][e];
#pragma unroll
    for (int i = 0; i < 32; i++) {
        int idx = base + i;
        int e   = eidx[i];
        int pos = run[e]++;
        if (pos < CAP) {
            int s = idx >> 1;
            g_disp_tok[e * CAP + pos] = s;
            g_slot[idx] = e * CAP + pos;
            g_wt[idx]   = g_topk_gate[idx];
        } else {
            g_slot[idx] = -1;
            g_wt[idx]   = 0.f;
        }
    }
}

// ---------------- 3+4) TF32 tensor-core GEMM ---------------------------------------
// C[e,m,n] = (relu?) A[e,m,:] @ B[e,:,n]
// A rows gathered via g_disp_tok when GATHER. Block tile 128x128, BK=16,
// warp tile 64x32 (m16n8k8 frags, 4x4 per warp), cp.async double buffer.
template <int KDIM, bool GATHER, bool RELU>
__global__ __launch_bounds__(256, 2)
void gemm_tc(const float* __restrict__ Abase, const float* __restrict__ Bbase,
             float* __restrict__ Cbase, const int N) {
    constexpr int BM = 128, BN = 128, BK = 16;
    constexpr int ASTR = BK + 4;    // 20 floats -> conflict-free A frag loads
    constexpr int BSTR = BN + 8;    // 136 floats -> conflict-free B frag loads
    constexpr int ASZ = BM * ASTR;  // floats per stage
    constexpr int BSZ = BK * BSTR;

    __shared__ float As[2 * ASZ];
    __shared__ float Bs[2 * BSZ];
    __shared__ int   stoks[BM];

    const int e  = blockIdx.z;
    const int m0 = blockIdx.y * BM;
    const int n0 = blockIdx.x * BN;

    const int tid  = threadIdx.x;
    const int lane = tid & 31, wid = tid >> 5;
    const int gid  = lane >> 2, t4 = lane & 3;
    const int warpM = wid >> 2, warpN = wid & 3;  // 2 x 4 warp grid

    if (GATHER) {
        if (tid < BM) stoks[tid] = g_disp_tok[e * CAP + m0 + tid];
        __syncthreads();
    }

    // A stage = 128 rows x 16 floats = 512 x 16B chunks; thread owns chunks tid, tid+256
    const int arow0 = tid >> 2;              // 0..63
    const int arow1 = arow0 + 64;
    const int akq   = (tid & 3) * 4;         // k offset (floats)
    const float* aptr0;
    const float* aptr1;
    if (GATHER) {
        aptr0 = Abase + (size_t)stoks[arow0] * KDIM + akq;
        aptr1 = Abase + (size_t)stoks[arow1] * KDIM + akq;
    } else {
        aptr0 = Abase + ((size_t)e * CAP + m0 + arow0) * KDIM + akq;
        aptr1 = Abase + ((size_t)e * CAP + m0 + arow1) * KDIM + akq;
    }

    // B stage = 16 rows x 128 floats = 512 x 16B chunks; thread owns rows wid, wid+8
    const int bnq = lane * 4;
    const float* bptr0 = Bbase + (size_t)e * KDIM * N + (size_t)wid * N + n0 + bnq;
    const float* bptr1 = bptr0 + (size_t)8 * N;

    const uint32_t sA = (uint32_t)__cvta_generic_to_shared(As);
    const uint32_t sB = (uint32_t)__cvta_generic_to_shared(Bs);
    const uint32_t dA0 = sA + (arow0 * ASTR + akq) * 4;
    const uint32_t dA1 = sA + (arow1 * ASTR + akq) * 4;
    const uint32_t dB0 = sB + (wid * BSTR + bnq) * 4;
    const uint32_t dB1 = sB + ((wid + 8) * BSTR + bnq) * 4;

    float d[4][4][4];
#pragma unroll
    for (int i = 0; i < 4; i++)
#pragma unroll
        for (int j = 0; j < 4; j++)
#pragma unroll
            for (int r = 0; r < 4; r++) d[i][j][r] = 0.f;

    constexpr int KT = KDIM / BK;

    auto issue = [&](int kt, int buf) {
        const size_t ko = (size_t)kt * BK;
        const uint32_t ao = buf ? (uint32_t)(ASZ * 4) : 0u;
        const uint32_t bo = buf ? (uint32_t)(BSZ * 4) : 0u;
        cp_async16(dA0 + ao, aptr0 + ko);
        cp_async16(dA1 + ao, aptr1 + ko);
        cp_async16(dB0 + bo, bptr0 + ko * N);
        cp_async16(dB1 + bo, bptr1 + ko * N);
        cp_commit();
    };

    issue(0, 0);

#pragma unroll 1
    for (int kt = 0; kt < KT; kt++) {
        const int buf = kt & 1;
        if (kt + 1 < KT) {
            issue(kt + 1, buf ^ 1);
            cp_wait<1>();
        } else {
            cp_wait<0>();
        }
        __syncthreads();

        const float* as = As + buf * ASZ;
        const float* bs = Bs + buf * BSZ;

#pragma unroll
        for (int kk = 0; kk < BK; kk += 8) {
            uint32_t af[4][4], bf[4][2];
#pragma unroll
            for (int i = 0; i < 4; i++) {
                const int m = warpM * 64 + i * 16 + gid;
                const float* a = as + m * ASTR + kk + t4;
                af[i][0] = f2tf(a[0]);
                af[i][1] = f2tf(a[8 * ASTR]);
                af[i][2] = f2tf(a[4]);
                af[i][3] = f2tf(a[8 * ASTR + 4]);
            }
#pragma unroll
            for (int j = 0; j < 4; j++) {
                const int n = warpN * 32 + j * 8 + gid;
                const float* b = bs + (kk + t4) * BSTR + n;
                bf[j][0] = f2tf(b[0]);
                bf[j][1] = f2tf(b[4 * BSTR]);
            }
#pragma unroll
            for (int i = 0; i < 4; i++)
#pragma unroll
                for (int j = 0; j < 4; j++)
                    mma_tf32(d[i][j], af[i], bf[j]);
        }
        __syncthreads();
    }

    // epilogue
    float* C = Cbase + ((size_t)e * CAP + m0) * N + n0;
#pragma unroll
    for (int i = 0; i < 4; i++) {
        const int mrow = warpM * 64 + i * 16 + gid;
#pragma unroll
        for (int j = 0; j < 4; j++) {
            const int ncol = warpN * 32 + j * 8 + t4 * 2;
            float2 v0 = make_float2(d[i][j][0], d[i][j][1]);
            float2 v1 = make_float2(d[i][j][2], d[i][j][3]);
            if (RELU) {
                v0.x = fmaxf(v0.x, 0.f); v0.y = fmaxf(v0.y, 0.f);
                v1.x = fmaxf(v1.x, 0.f); v1.y = fmaxf(v1.y, 0.f);
            }
            *(float2*)(C + (size_t)mrow * N + ncol)       = v0;
            *(float2*)(C + (size_t)(mrow + 8) * N + ncol) = v1;
        }
    }
}

// ---------------- 5) combine: out[s,:] = sum_j w_j * Eout[slot_j,:] -----------------
__global__ void combine_kernel(float* __restrict__ out) {
    const int s = blockIdx.x;
    const int sl0 = g_slot[s * 2 + 0];
    const int sl1 = g_slot[s * 2 + 1];
    const float w0 = g_wt[s * 2 + 0];
    const float w1 = g_wt[s * 2 + 1];

    const float4* e0 = (sl0 >= 0) ? (const float4*)(g_Eout + (size_t)sl0 * DMODEL) : nullptr;
    const float4* e1 = (sl1 >= 0) ? (const float4*)(g_Eout + (size_t)sl1 * DMODEL) : nullptr;
    float4* dst = (float4*)(out + (size_t)s * DMODEL);

    for (int m = threadIdx.x; m < DMODEL / 4; m += blockDim.x) {
        float4 r = make_float4(0.f, 0.f, 0.f, 0.f);
        if (e0) {
            float4 v = e0[m];
            r.x = fmaf(w0, v.x, r.x); r.y = fmaf(w0, v.y, r.y);
            r.z = fmaf(w0, v.z, r.z); r.w = fmaf(w0, v.w, r.w);
        }
        if (e1) {
            float4 v = e1[m];
            r.x = fmaf(w1, v.x, r.x); r.y = fmaf(w1, v.y, r.y);
            r.z = fmaf(w1, v.z, r.z); r.w = fmaf(w1, v.w, r.w);
        }
        dst[m] = r;
    }
}

// ---------------- launch -----------------------------------------------------------
extern "C" void kernel_launch(void* const* d_in, const int* in_sizes, int n_in,
                              void* d_out, int out_size) {
    const float* x  = (const float*)d_in[0];
    const float* Wg = (const float*)d_in[1];
    const float* w1 = (const float*)d_in[2];
    const float* w2 = (const float*)d_in[3];
    float* out = (float*)d_out;

    gate_kernel<<<(S_TOK * 32 + 255) / 256, 256>>>(x, Wg);
    route_kernel<<<1, 512>>>();

    float* Hp = nullptr;   cudaGetSymbolAddress((void**)&Hp, g_H);
    float* Ep = nullptr;   cudaGetSymbolAddress((void**)&Ep, g_Eout);

    dim3 g1(DFF / 128, CAP / 128, NEXP);     // (64, 20, 8)
    gemm_tc<DMODEL, true, true><<<g1, 256>>>(x, w1, Hp, DFF);

    dim3 g2(DMODEL / 128, CAP / 128, NEXP);  // (16, 20, 8)
    gemm_tc<DFF, false, false><<<g2, 256>>>(Hp, w2, Ep, DMODEL);

    combine_kernel<<<S_TOK, 128>>>(out);
}